// round 15
// baseline (speedup 1.0000x reference)
#include <cuda_runtime.h>
#include <cuda_fp16.h>

// ---------------------------------------------------------------------------
// Hetero-GNN (5 hetero_conv layers) over N=100000 nodes.
// R15 = R14 (fp16 gather mirrors, 8 edges/warp-iter) with the fp16 mirror
//       DOUBLE-BUFFERED (g_hh/g_hh2) to fix the R14 in-place read/write race.
// ---------------------------------------------------------------------------

#define N_NODES 100000
#define WPB 12
#define NPB (WPB * 4)

__device__ float  g_h    [N_NODES * 32];
__device__ float  g_h2   [N_NODES * 32];
__device__ __half g_hh   [N_NODES * 32];   // fp16 mirror, buffer A
__device__ __half g_hh2  [N_NODES * 32];   // fp16 mirror, buffer B
__device__ float  g_x8   [N_NODES * 8];
__device__ __half g_x16  [N_NODES * 8];
__device__ float  g_dummy[N_NODES * 32];

__device__ int g_deg_t[N_NODES];
__device__ int g_deg_i[N_NODES];
__device__ int g_rpt  [N_NODES + 1];
__device__ int g_rpi  [N_NODES + 1];
__device__ int g_bsum_t[1024];
__device__ int g_bsum_i[1024];
__device__ int g_col_t[100000];
__device__ int g_col_i[3200000];

// Unpack uint4 (8 fp16) and predicated-accumulate into a[0..7]
__device__ __forceinline__ void acc8(uint4 v, bool on, float* a) {
    float2 f;
    f = __half22float2(*reinterpret_cast<__half2*>(&v.x));
    if (on) { a[0] += f.x; a[1] += f.y; }
    f = __half22float2(*reinterpret_cast<__half2*>(&v.y));
    if (on) { a[2] += f.x; a[3] += f.y; }
    f = __half22float2(*reinterpret_cast<__half2*>(&v.z));
    if (on) { a[4] += f.x; a[5] += f.y; }
    f = __half22float2(*reinterpret_cast<__half2*>(&v.w));
    if (on) { a[6] += f.x; a[7] += f.y; }
}

// ---------------------------------------------------------------------------
// CSR build (identical to champion)
// ---------------------------------------------------------------------------
__global__ void zero2_kernel(int* __restrict__ a, int* __restrict__ b, int n) {
    int i = blockIdx.x * blockDim.x + threadIdx.x;
    if (i < n) { a[i] = 0; b[i] = 0; }
}

__global__ void count_kernel(const int* __restrict__ dst, int E, int* __restrict__ deg) {
    int i = blockIdx.x * blockDim.x + threadIdx.x;
    if (i < E) atomicAdd(&deg[dst[i]], 1);
}

__global__ void scan_p1(const int* __restrict__ deg, int* __restrict__ rowptr,
                        int* __restrict__ bsum, int n) {
    __shared__ int sh[1024];
    int i = blockIdx.x * 1024 + threadIdx.x;
    int v = (i < n) ? deg[i] : 0;
    sh[threadIdx.x] = v;
    __syncthreads();
    for (int off = 1; off < 1024; off <<= 1) {
        int t = (threadIdx.x >= off) ? sh[threadIdx.x - off] : 0;
        __syncthreads();
        sh[threadIdx.x] += t;
        __syncthreads();
    }
    if (i < n) rowptr[i] = sh[threadIdx.x] - v;
    if (threadIdx.x == 1023) bsum[blockIdx.x] = sh[1023];
}

__global__ void scan_p2(int* __restrict__ bsum, int nb) {
    __shared__ int sh[1024];
    int v = (threadIdx.x < nb) ? bsum[threadIdx.x] : 0;
    sh[threadIdx.x] = v;
    __syncthreads();
    for (int off = 1; off < 1024; off <<= 1) {
        int t = (threadIdx.x >= off) ? sh[threadIdx.x - off] : 0;
        __syncthreads();
        sh[threadIdx.x] += t;
        __syncthreads();
    }
    if (threadIdx.x < nb) bsum[threadIdx.x] = sh[threadIdx.x] - v;
}

__global__ void scan_p3(int* __restrict__ rowptr, const int* __restrict__ bsum,
                        int* __restrict__ cursor, int n, int E) {
    int i = blockIdx.x * blockDim.x + threadIdx.x;
    if (i < n) {
        int v = rowptr[i] + bsum[i >> 10];
        rowptr[i] = v;
        cursor[i] = v;
    }
    if (i == 0) rowptr[n] = E;
}

__global__ void fill_kernel(const int* __restrict__ src, const int* __restrict__ dst,
                            int E, int* __restrict__ cursor, int* __restrict__ col) {
    int i = blockIdx.x * blockDim.x + threadIdx.x;
    if (i < E) {
        int d = dst[i];
        int p = atomicAdd(&cursor[d], 1);
        col[p] = src[i];
    }
}

__global__ void repack_x(const float* __restrict__ x, float* __restrict__ x8,
                         __half* __restrict__ x16, int n) {
    int i = blockIdx.x * blockDim.x + threadIdx.x;
    if (i < n * 8) {
        int node = i >> 3, c = i & 7;
        float v = (c < 6) ? x[node * 6 + c] : 0.f;
        x8[i] = v;
        x16[i] = __float2half(v);
    }
}

// ---------------------------------------------------------------------------
// Fused HIDDEN layer (32->32, residual). fp16 gather, 8 edges/warp-iter.
// Reads (h, hhin); writes (hout, hhout). hhin != hhout (double-buffered).
// ---------------------------------------------------------------------------
__global__ void __launch_bounds__(WPB * 32)
fused_hidden3(const float* __restrict__ h, const __half* __restrict__ hhin,
              const int* __restrict__ rpt, const int* __restrict__ colt,
              const int* __restrict__ rpi, const int* __restrict__ coli,
              const float* __restrict__ Wt, const float* __restrict__ Wi,
              const float* __restrict__ Wr, const float* __restrict__ b,
              float* __restrict__ hout, __half* __restrict__ hhout, int n) {
    __shared__ float4 sW4[32 * 32];
    __shared__ float4 sV[WPB * 4 * 32];
    __shared__ float  sB[32];

    for (int i = threadIdx.x; i < 32 * 32; i += blockDim.x) {
        int ci = i >> 5, l = i & 31;
        sW4[i] = make_float4(Wt[ci * 32 + l], Wi[ci * 32 + l], Wr[ci * 32 + l], 0.f);
    }
    if (threadIdx.x < 32) sB[threadIdx.x] = b[threadIdx.x];
    __syncthreads();

    int warp = threadIdx.x >> 5, lane = threadIdx.x & 31;
    int node0 = (blockIdx.x * WPB + warp) * 4;
    if (node0 >= n) return;
    int g = lane >> 2, c = lane & 3;
    const uint4*  hq = (const uint4*)hhin;
    const float4* h4 = (const float4*)h;
    float4* vbase = &sV[warp * 128];

#pragma unroll
    for (int j = 0; j < 4; j++) {
        int node = node0 + j;
        if (node >= n) break;

        float aT[8] = {0,0,0,0,0,0,0,0};
        float aM[8] = {0,0,0,0,0,0,0,0};

        int b0 = rpt[node], e0 = rpt[node + 1];
        for (int e = b0; e < e0; e += 8) {
            int ei = e + g;
            int ec = (ei < e0) ? ei : (e0 - 1);
            int s = colt[ec];
            uint4 v = hq[s * 4 + c];
            acc8(v, ei < e0, aT);
        }

        int b1 = rpi[node], e1 = rpi[node + 1];
        for (int e = b1; e < e1; e += 8) {
            int ei = e + g;
            int ec = (ei < e1) ? ei : (e1 - 1);
            int s = coli[ec];
            uint4 v = hq[s * 4 + c];
            acc8(v, ei < e1, aM);
        }

#pragma unroll
        for (int off = 4; off <= 16; off <<= 1) {
#pragma unroll
            for (int k = 0; k < 8; k++) {
                aT[k] += __shfl_xor_sync(0xffffffffu, aT[k], off);
                aM[k] += __shfl_xor_sync(0xffffffffu, aM[k], off);
            }
        }
        float invd = 1.0f / fmaxf((float)(e1 - b1), 1.0f);

        if (lane < 4) {
            float4 hva = h4[node * 8 + lane * 2];
            float4 hvb = h4[node * 8 + lane * 2 + 1];
            float hv[8] = {hva.x, hva.y, hva.z, hva.w, hvb.x, hvb.y, hvb.z, hvb.w};
#pragma unroll
            for (int k = 0; k < 8; k++)
                vbase[j * 32 + lane * 8 + k] = make_float4(aT[k], aM[k] * invd, hv[k], 0.f);
        }
    }
    __syncwarp();

    float acc0 = sB[lane], acc1 = sB[lane], acc2 = sB[lane], acc3 = sB[lane];
#pragma unroll
    for (int ci = 0; ci < 32; ci++) {
        float4 w = sW4[ci * 32 + lane];
        float4 v0 = vbase[0 * 32 + ci];
        float4 v1 = vbase[1 * 32 + ci];
        float4 v2 = vbase[2 * 32 + ci];
        float4 v3 = vbase[3 * 32 + ci];
        acc0 += v0.x * w.x + v0.y * w.y + v0.z * w.z;
        acc1 += v1.x * w.x + v1.y * w.y + v1.z * w.z;
        acc2 += v2.x * w.x + v2.y * w.y + v2.z * w.z;
        acc3 += v3.x * w.x + v3.y * w.y + v3.z * w.z;
    }
    float accs[4] = {acc0, acc1, acc2, acc3};
#pragma unroll
    for (int j = 0; j < 4; j++) {
        int node = node0 + j;
        if (node < n) {
            float hv = vbase[j * 32 + lane].z;
            float r = fmaxf(accs[j], 0.f) + hv;
            hout[node * 32 + lane] = r;
            hhout[node * 32 + lane] = __float2half(r);
        }
    }
}

// ---------------------------------------------------------------------------
// Fused HEAD layer (6->32). fp16 x16 gather: 32 edges/warp-iter.
// ---------------------------------------------------------------------------
__global__ void __launch_bounds__(WPB * 32)
fused_head3(const float* __restrict__ x8, const __half* __restrict__ x16,
            const int* __restrict__ rpt, const int* __restrict__ colt,
            const int* __restrict__ rpi, const int* __restrict__ coli,
            const float* __restrict__ Wt, const float* __restrict__ Wi,
            const float* __restrict__ Wr, const float* __restrict__ b,
            float* __restrict__ hout, __half* __restrict__ hhout, int n) {
    __shared__ float4 sW4[6 * 32];
    __shared__ float4 sV[WPB * 4 * 8];
    __shared__ float  sB[32];

    for (int i = threadIdx.x; i < 6 * 32; i += blockDim.x) {
        int ci = i >> 5, l = i & 31;
        sW4[i] = make_float4(Wt[ci * 32 + l], Wi[ci * 32 + l], Wr[ci * 32 + l], 0.f);
    }
    if (threadIdx.x < 32) sB[threadIdx.x] = b[threadIdx.x];
    __syncthreads();

    int warp = threadIdx.x >> 5, lane = threadIdx.x & 31;
    int node0 = (blockIdx.x * WPB + warp) * 4;
    if (node0 >= n) return;
    const uint4*  xq = (const uint4*)x16;
    const float4* x4 = (const float4*)x8;
    float4* vbase = &sV[warp * 32];

#pragma unroll
    for (int j = 0; j < 4; j++) {
        int node = node0 + j;
        if (node >= n) break;

        float aT[8] = {0,0,0,0,0,0,0,0};
        float aM[8] = {0,0,0,0,0,0,0,0};

        int b0 = rpt[node], e0 = rpt[node + 1];
        for (int e = b0; e < e0; e += 32) {
            int ei = e + lane;
            int ec = (ei < e0) ? ei : (e0 - 1);
            int s = colt[ec];
            uint4 v = xq[s];
            acc8(v, ei < e0, aT);
        }

        int b1 = rpi[node], e1 = rpi[node + 1];
        for (int e = b1; e < e1; e += 32) {
            int ei = e + lane;
            int ec = (ei < e1) ? ei : (e1 - 1);
            int s = coli[ec];
            uint4 v = xq[s];
            acc8(v, ei < e1, aM);
        }

#pragma unroll
        for (int off = 1; off <= 16; off <<= 1) {
#pragma unroll
            for (int k = 0; k < 8; k++) {
                aT[k] += __shfl_xor_sync(0xffffffffu, aT[k], off);
                aM[k] += __shfl_xor_sync(0xffffffffu, aM[k], off);
            }
        }
        float invd = 1.0f / fmaxf((float)(e1 - b1), 1.0f);

        if (lane == 0) {
            float4 xa = x4[node * 2];
            float4 xb = x4[node * 2 + 1];
            float xv[8] = {xa.x, xa.y, xa.z, xa.w, xb.x, xb.y, xb.z, xb.w};
#pragma unroll
            for (int k = 0; k < 8; k++)
                vbase[j * 8 + k] = make_float4(aT[k], aM[k] * invd, xv[k], 0.f);
        }
    }
    __syncwarp();

    float acc0 = sB[lane], acc1 = sB[lane], acc2 = sB[lane], acc3 = sB[lane];
#pragma unroll
    for (int ci = 0; ci < 6; ci++) {
        float4 w = sW4[ci * 32 + lane];
        float4 v0 = vbase[0 * 8 + ci];
        float4 v1 = vbase[1 * 8 + ci];
        float4 v2 = vbase[2 * 8 + ci];
        float4 v3 = vbase[3 * 8 + ci];
        acc0 += v0.x * w.x + v0.y * w.y + v0.z * w.z;
        acc1 += v1.x * w.x + v1.y * w.y + v1.z * w.z;
        acc2 += v2.x * w.x + v2.y * w.y + v2.z * w.z;
        acc3 += v3.x * w.x + v3.y * w.y + v3.z * w.z;
    }
    float accs[4] = {acc0, acc1, acc2, acc3};
#pragma unroll
    for (int j = 0; j < 4; j++) {
        int node = node0 + j;
        if (node < n) {
            float r = fmaxf(accs[j], 0.f);
            hout[node * 32 + lane] = r;
            hhout[node * 32 + lane] = __float2half(r);
        }
    }
}

// ---------------------------------------------------------------------------
// Fused LAST layer (32->64 + projection residual). fp16 gather.
// ---------------------------------------------------------------------------
__global__ void __launch_bounds__(WPB * 32)
fused_last3(const float* __restrict__ h, const __half* __restrict__ hhin,
            const int* __restrict__ rpt, const int* __restrict__ colt,
            const int* __restrict__ rpi, const int* __restrict__ coli,
            const float* __restrict__ Wt, const float* __restrict__ Wi,
            const float* __restrict__ Wr, const float* __restrict__ b,
            const float* __restrict__ Wp,
            float* __restrict__ out, int n) {
    __shared__ float4 sW4a[32 * 32];
    __shared__ float4 sW4b[32 * 32];
    __shared__ float4 sV[WPB * 4 * 32];

    for (int i = threadIdx.x; i < 32 * 32; i += blockDim.x) {
        int ci = i >> 5, l = i & 31;
        sW4a[i] = make_float4(Wt[ci * 64 + l],      Wi[ci * 64 + l],      Wr[ci * 64 + l],      Wp[ci * 64 + l]);
        sW4b[i] = make_float4(Wt[ci * 64 + l + 32], Wi[ci * 64 + l + 32], Wr[ci * 64 + l + 32], Wp[ci * 64 + l + 32]);
    }
    __syncthreads();

    int warp = threadIdx.x >> 5, lane = threadIdx.x & 31;
    int node0 = (blockIdx.x * WPB + warp) * 4;
    if (node0 >= n) return;
    int g = lane >> 2, c = lane & 3;
    const uint4*  hq = (const uint4*)hhin;
    const float4* h4 = (const float4*)h;
    float4* vbase = &sV[warp * 128];

    float bias0 = b[lane], bias1 = b[lane + 32];

#pragma unroll
    for (int j = 0; j < 4; j++) {
        int node = node0 + j;
        if (node >= n) break;

        float aT[8] = {0,0,0,0,0,0,0,0};
        float aM[8] = {0,0,0,0,0,0,0,0};

        int b0 = rpt[node], e0 = rpt[node + 1];
        for (int e = b0; e < e0; e += 8) {
            int ei = e + g;
            int ec = (ei < e0) ? ei : (e0 - 1);
            int s = colt[ec];
            uint4 v = hq[s * 4 + c];
            acc8(v, ei < e0, aT);
        }

        int b1 = rpi[node], e1 = rpi[node + 1];
        for (int e = b1; e < e1; e += 8) {
            int ei = e + g;
            int ec = (ei < e1) ? ei : (e1 - 1);
            int s = coli[ec];
            uint4 v = hq[s * 4 + c];
            acc8(v, ei < e1, aM);
        }

#pragma unroll
        for (int off = 4; off <= 16; off <<= 1) {
#pragma unroll
            for (int k = 0; k < 8; k++) {
                aT[k] += __shfl_xor_sync(0xffffffffu, aT[k], off);
                aM[k] += __shfl_xor_sync(0xffffffffu, aM[k], off);
            }
        }
        float invd = 1.0f / fmaxf((float)(e1 - b1), 1.0f);

        if (lane < 4) {
            float4 hva = h4[node * 8 + lane * 2];
            float4 hvb = h4[node * 8 + lane * 2 + 1];
            float hv[8] = {hva.x, hva.y, hva.z, hva.w, hvb.x, hvb.y, hvb.z, hvb.w};
#pragma unroll
            for (int k = 0; k < 8; k++)
                vbase[j * 32 + lane * 8 + k] = make_float4(aT[k], aM[k] * invd, hv[k], 0.f);
        }
    }
    __syncwarp();

    float a0[4], a1[4], p0[4], p1[4];
#pragma unroll
    for (int j = 0; j < 4; j++) { a0[j] = bias0; a1[j] = bias1; p0[j] = 0.f; p1[j] = 0.f; }

#pragma unroll
    for (int ci = 0; ci < 32; ci++) {
        float4 wa = sW4a[ci * 32 + lane];
        float4 wb = sW4b[ci * 32 + lane];
#pragma unroll
        for (int j = 0; j < 4; j++) {
            float4 v = vbase[j * 32 + ci];
            a0[j] += v.x * wa.x + v.y * wa.y + v.z * wa.z;
            p0[j] += v.z * wa.w;
            a1[j] += v.x * wb.x + v.y * wb.y + v.z * wb.z;
            p1[j] += v.z * wb.w;
        }
    }
#pragma unroll
    for (int j = 0; j < 4; j++) {
        int node = node0 + j;
        if (node < n) {
            out[node * 64 + lane]      = fmaxf(a0[j], 0.f) + p0[j];
            out[node * 64 + lane + 32] = fmaxf(a1[j], 0.f) + p1[j];
        }
    }
}

// ---------------------------------------------------------------------------
// Launch
// ---------------------------------------------------------------------------
extern "C" void kernel_launch(void* const* d_in, const int* in_sizes, int n_in,
                              void* d_out, int out_size) {
    const float* x        = (const float*)d_in[0];
    const int*   ei_t     = (const int*)d_in[1];
    const int*   ei_i     = (const int*)d_in[2];
    const float* head_Wt  = (const float*)d_in[3];
    const float* head_Wi  = (const float*)d_in[4];
    const float* head_Wr  = (const float*)d_in[5];
    const float* head_b   = (const float*)d_in[6];
    const float* blk_Wt   = (const float*)d_in[7];
    const float* blk_Wi   = (const float*)d_in[8];
    const float* blk_Wr   = (const float*)d_in[9];
    const float* blk_b    = (const float*)d_in[10];
    const float* last_Wt  = (const float*)d_in[11];
    const float* last_Wi  = (const float*)d_in[12];
    const float* last_Wr  = (const float*)d_in[13];
    const float* last_b   = (const float*)d_in[14];
    const float* last_proj= (const float*)d_in[15];

    const int n  = in_sizes[0] / 6;
    const int Et = in_sizes[1] / 2;
    const int Ei = in_sizes[2] / 2;

    float *h, *h2, *x8, *dmy;
    __half *hh, *hh2, *x16;
    int *degt, *degi, *rpt, *rpi, *colt, *coli, *bst, *bsi;
    cudaGetSymbolAddress((void**)&h,    g_h);
    cudaGetSymbolAddress((void**)&h2,   g_h2);
    cudaGetSymbolAddress((void**)&hh,   g_hh);
    cudaGetSymbolAddress((void**)&hh2,  g_hh2);
    cudaGetSymbolAddress((void**)&x8,   g_x8);
    cudaGetSymbolAddress((void**)&x16,  g_x16);
    cudaGetSymbolAddress((void**)&dmy,  g_dummy);
    cudaGetSymbolAddress((void**)&degt, g_deg_t);
    cudaGetSymbolAddress((void**)&degi, g_deg_i);
    cudaGetSymbolAddress((void**)&rpt,  g_rpt);
    cudaGetSymbolAddress((void**)&rpi,  g_rpi);
    cudaGetSymbolAddress((void**)&bst,  g_bsum_t);
    cudaGetSymbolAddress((void**)&bsi,  g_bsum_i);
    cudaGetSymbolAddress((void**)&colt, g_col_t);
    cudaGetSymbolAddress((void**)&coli, g_col_i);

    const int T = 256;
    const int TB = WPB * 32;
    int nb = (n + 1023) / 1024;
    int nodeBlocks = (n + NPB - 1) / NPB;

    zero2_kernel<<<(n + T - 1) / T, T>>>(degt, degi, n);
    count_kernel<<<(Et + T - 1) / T, T>>>(ei_t + Et, Et, degt);
    count_kernel<<<(Ei + T - 1) / T, T>>>(ei_i + Ei, Ei, degi);

    // Launch 3 (ncu capture slot): DUMMY fused_hidden3 on 12.5k nodes.
    {
        const int nd = 12500;
        fused_hidden3<<<(nd + NPB - 1) / NPB, TB>>>(h, hh, rpt, colt, rpi, coli,
                                                    blk_Wt, blk_Wi, blk_Wr, blk_b,
                                                    dmy, (__half*)dmy, nd);
    }

    repack_x<<<(n * 8 + T - 1) / T, T>>>(x, x8, x16, n);

    scan_p1<<<nb, 1024>>>(degt, rpt, bst, n);
    scan_p1<<<nb, 1024>>>(degi, rpi, bsi, n);
    scan_p2<<<1, 1024>>>(bst, nb);
    scan_p2<<<1, 1024>>>(bsi, nb);
    scan_p3<<<(n + T) / T, T>>>(rpt, bst, degt, n, Et);
    scan_p3<<<(n + T) / T, T>>>(rpi, bsi, degi, n, Ei);
    fill_kernel<<<(Et + T - 1) / T, T>>>(ei_t, ei_t + Et, Et, degt, colt);
    fill_kernel<<<(Ei + T - 1) / T, T>>>(ei_i, ei_i + Ei, Ei, degi, coli);

    // --- head: 6 -> 32 ---
    fused_head3<<<nodeBlocks, TB>>>(x8, x16, rpt, colt, rpi, coli,
                                    head_Wt, head_Wi, head_Wr, head_b, h, hh, n);

    // --- 3 residual blocks: 32 -> 32 (double-buffered h AND hh) ---
    for (int i = 0; i < 3; i++) {
        fused_hidden3<<<nodeBlocks, TB>>>(h, hh, rpt, colt, rpi, coli,
                                          blk_Wt + i * 32 * 32, blk_Wi + i * 32 * 32,
                                          blk_Wr + i * 32 * 32, blk_b + i * 32,
                                          h2, hh2, n);
        float* tf = h; h = h2; h2 = tf;
        __half* th = hh; hh = hh2; hh2 = th;
    }

    // --- last: 32 -> 64 ---
    fused_last3<<<nodeBlocks, TB>>>(h, hh, rpt, colt, rpi, coli,
                                    last_Wt, last_Wi, last_Wr, last_b, last_proj,
                                    (float*)d_out, n);
}

// round 16
// speedup vs baseline: 1.1380x; 1.1380x over previous
#include <cuda_runtime.h>
#include <cuda_fp16.h>

// ---------------------------------------------------------------------------
// Hetero-GNN (5 hetero_conv layers) over N=100000 nodes.
// R16 = R13 (champion, 533.6us) with the diagnostic dummy probe REMOVED.
//   - MIO-lean fused layers: float4 edge-group gather (4 edges/warp-iter,
//     8-lane groups), smem-staged combine with packed float4 weights.
//   - 384-thread blocks (12 warps x 4 nodes), ~40KB smem.
// ---------------------------------------------------------------------------

#define N_NODES 100000
#define WPB 12                      // warps per block (node kernels)
#define NPB (WPB * 4)               // nodes per block

__device__ float g_h  [N_NODES * 32];
__device__ float g_h2 [N_NODES * 32];
__device__ float g_x8 [N_NODES * 8];

__device__ int g_deg_t[N_NODES];
__device__ int g_deg_i[N_NODES];
__device__ int g_rpt  [N_NODES + 1];
__device__ int g_rpi  [N_NODES + 1];
__device__ int g_bsum_t[1024];
__device__ int g_bsum_i[1024];
__device__ int g_col_t[100000];
__device__ int g_col_i[3200000];

// ---------------------------------------------------------------------------
// CSR build
// ---------------------------------------------------------------------------
__global__ void zero2_kernel(int* __restrict__ a, int* __restrict__ b, int n) {
    int i = blockIdx.x * blockDim.x + threadIdx.x;
    if (i < n) { a[i] = 0; b[i] = 0; }
}

__global__ void count_kernel(const int* __restrict__ dst, int E, int* __restrict__ deg) {
    int i = blockIdx.x * blockDim.x + threadIdx.x;
    if (i < E) atomicAdd(&deg[dst[i]], 1);
}

__global__ void scan_p1(const int* __restrict__ deg, int* __restrict__ rowptr,
                        int* __restrict__ bsum, int n) {
    __shared__ int sh[1024];
    int i = blockIdx.x * 1024 + threadIdx.x;
    int v = (i < n) ? deg[i] : 0;
    sh[threadIdx.x] = v;
    __syncthreads();
    for (int off = 1; off < 1024; off <<= 1) {
        int t = (threadIdx.x >= off) ? sh[threadIdx.x - off] : 0;
        __syncthreads();
        sh[threadIdx.x] += t;
        __syncthreads();
    }
    if (i < n) rowptr[i] = sh[threadIdx.x] - v;
    if (threadIdx.x == 1023) bsum[blockIdx.x] = sh[1023];
}

__global__ void scan_p2(int* __restrict__ bsum, int nb) {
    __shared__ int sh[1024];
    int v = (threadIdx.x < nb) ? bsum[threadIdx.x] : 0;
    sh[threadIdx.x] = v;
    __syncthreads();
    for (int off = 1; off < 1024; off <<= 1) {
        int t = (threadIdx.x >= off) ? sh[threadIdx.x - off] : 0;
        __syncthreads();
        sh[threadIdx.x] += t;
        __syncthreads();
    }
    if (threadIdx.x < nb) bsum[threadIdx.x] = sh[threadIdx.x] - v;
}

__global__ void scan_p3(int* __restrict__ rowptr, const int* __restrict__ bsum,
                        int* __restrict__ cursor, int n, int E) {
    int i = blockIdx.x * blockDim.x + threadIdx.x;
    if (i < n) {
        int v = rowptr[i] + bsum[i >> 10];
        rowptr[i] = v;
        cursor[i] = v;
    }
    if (i == 0) rowptr[n] = E;
}

__global__ void fill_kernel(const int* __restrict__ src, const int* __restrict__ dst,
                            int E, int* __restrict__ cursor, int* __restrict__ col) {
    int i = blockIdx.x * blockDim.x + threadIdx.x;
    if (i < E) {
        int d = dst[i];
        int p = atomicAdd(&cursor[d], 1);
        col[p] = src[i];
    }
}

__global__ void repack_x8(const float* __restrict__ x, float* __restrict__ x8, int n) {
    int i = blockIdx.x * blockDim.x + threadIdx.x;
    if (i < n * 8) {
        int node = i >> 3, c = i & 7;
        x8[i] = (c < 6) ? x[node * 6 + c] : 0.f;
    }
}

// ---------------------------------------------------------------------------
// Fused HIDDEN layer (32->32, residual). WPB warps x 4 nodes.
// ---------------------------------------------------------------------------
__global__ void __launch_bounds__(WPB * 32)
fused_hidden2(const float* __restrict__ h,
              const int* __restrict__ rpt, const int* __restrict__ colt,
              const int* __restrict__ rpi, const int* __restrict__ coli,
              const float* __restrict__ Wt, const float* __restrict__ Wi,
              const float* __restrict__ Wr, const float* __restrict__ b,
              float* __restrict__ hout, int n) {
    __shared__ float4 sW4[32 * 32];          // 16 KB
    __shared__ float4 sV[WPB * 4 * 32];      // 24 KB
    __shared__ float  sB[32];

    for (int i = threadIdx.x; i < 32 * 32; i += blockDim.x) {
        int ci = i >> 5, l = i & 31;
        sW4[i] = make_float4(Wt[ci * 32 + l], Wi[ci * 32 + l], Wr[ci * 32 + l], 0.f);
    }
    if (threadIdx.x < 32) sB[threadIdx.x] = b[threadIdx.x];
    __syncthreads();

    int warp = threadIdx.x >> 5, lane = threadIdx.x & 31;
    int node0 = (blockIdx.x * WPB + warp) * 4;
    if (node0 >= n) return;
    int g = lane >> 3, c = lane & 7;
    const float4* h4 = (const float4*)h;
    float4* vbase = &sV[warp * 128];

#pragma unroll
    for (int j = 0; j < 4; j++) {
        int node = node0 + j;
        if (node >= n) break;

        float4 aT = make_float4(0.f, 0.f, 0.f, 0.f);
        float4 aM = make_float4(0.f, 0.f, 0.f, 0.f);

        int b0 = rpt[node], e0 = rpt[node + 1];
        for (int e = b0; e < e0; e += 4) {
            int ei = e + g;
            int ec = (ei < e0) ? ei : (e0 - 1);
            int s = colt[ec];
            float4 v = h4[s * 8 + c];
            if (ei < e0) { aT.x += v.x; aT.y += v.y; aT.z += v.z; aT.w += v.w; }
        }

        int b1 = rpi[node], e1 = rpi[node + 1];
        for (int e = b1; e < e1; e += 4) {
            int ei = e + g;
            int ec = (ei < e1) ? ei : (e1 - 1);
            int s = coli[ec];
            float4 v = h4[s * 8 + c];
            if (ei < e1) { aM.x += v.x; aM.y += v.y; aM.z += v.z; aM.w += v.w; }
        }

#pragma unroll
        for (int off = 8; off <= 16; off <<= 1) {
            aT.x += __shfl_xor_sync(0xffffffffu, aT.x, off);
            aT.y += __shfl_xor_sync(0xffffffffu, aT.y, off);
            aT.z += __shfl_xor_sync(0xffffffffu, aT.z, off);
            aT.w += __shfl_xor_sync(0xffffffffu, aT.w, off);
            aM.x += __shfl_xor_sync(0xffffffffu, aM.x, off);
            aM.y += __shfl_xor_sync(0xffffffffu, aM.y, off);
            aM.z += __shfl_xor_sync(0xffffffffu, aM.z, off);
            aM.w += __shfl_xor_sync(0xffffffffu, aM.w, off);
        }
        float invd = 1.0f / fmaxf((float)(e1 - b1), 1.0f);
        aM.x *= invd; aM.y *= invd; aM.z *= invd; aM.w *= invd;

        if (lane < 8) {
            float4 hv = h4[node * 8 + lane];
            vbase[j * 32 + lane * 4 + 0] = make_float4(aT.x, aM.x, hv.x, 0.f);
            vbase[j * 32 + lane * 4 + 1] = make_float4(aT.y, aM.y, hv.y, 0.f);
            vbase[j * 32 + lane * 4 + 2] = make_float4(aT.z, aM.z, hv.z, 0.f);
            vbase[j * 32 + lane * 4 + 3] = make_float4(aT.w, aM.w, hv.w, 0.f);
        }
    }
    __syncwarp();

    float acc0 = sB[lane], acc1 = sB[lane], acc2 = sB[lane], acc3 = sB[lane];
#pragma unroll
    for (int ci = 0; ci < 32; ci++) {
        float4 w = sW4[ci * 32 + lane];
        float4 v0 = vbase[0 * 32 + ci];
        float4 v1 = vbase[1 * 32 + ci];
        float4 v2 = vbase[2 * 32 + ci];
        float4 v3 = vbase[3 * 32 + ci];
        acc0 += v0.x * w.x + v0.y * w.y + v0.z * w.z;
        acc1 += v1.x * w.x + v1.y * w.y + v1.z * w.z;
        acc2 += v2.x * w.x + v2.y * w.y + v2.z * w.z;
        acc3 += v3.x * w.x + v3.y * w.y + v3.z * w.z;
    }
    float accs[4] = {acc0, acc1, acc2, acc3};
#pragma unroll
    for (int j = 0; j < 4; j++) {
        int node = node0 + j;
        if (node < n) {
            float hv = vbase[j * 32 + lane].z;
            hout[node * 32 + lane] = fmaxf(accs[j], 0.f) + hv;
        }
    }
}

// ---------------------------------------------------------------------------
// Fused HEAD layer (6->32). Padded x8 rows; 16 edge-groups x 2 lanes.
// ---------------------------------------------------------------------------
__global__ void __launch_bounds__(WPB * 32)
fused_head2(const float* __restrict__ x8,
            const int* __restrict__ rpt, const int* __restrict__ colt,
            const int* __restrict__ rpi, const int* __restrict__ coli,
            const float* __restrict__ Wt, const float* __restrict__ Wi,
            const float* __restrict__ Wr, const float* __restrict__ b,
            float* __restrict__ hout, int n) {
    __shared__ float4 sW4[6 * 32];
    __shared__ float4 sV[WPB * 4 * 8];
    __shared__ float  sB[32];

    for (int i = threadIdx.x; i < 6 * 32; i += blockDim.x) {
        int ci = i >> 5, l = i & 31;
        sW4[i] = make_float4(Wt[ci * 32 + l], Wi[ci * 32 + l], Wr[ci * 32 + l], 0.f);
    }
    if (threadIdx.x < 32) sB[threadIdx.x] = b[threadIdx.x];
    __syncthreads();

    int warp = threadIdx.x >> 5, lane = threadIdx.x & 31;
    int node0 = (blockIdx.x * WPB + warp) * 4;
    if (node0 >= n) return;
    int g = lane >> 1, c = lane & 1;
    const float4* x4 = (const float4*)x8;
    float4* vbase = &sV[warp * 32];

#pragma unroll
    for (int j = 0; j < 4; j++) {
        int node = node0 + j;
        if (node >= n) break;

        float4 aT = make_float4(0.f, 0.f, 0.f, 0.f);
        float4 aM = make_float4(0.f, 0.f, 0.f, 0.f);

        int b0 = rpt[node], e0 = rpt[node + 1];
        for (int e = b0; e < e0; e += 16) {
            int ei = e + g;
            int ec = (ei < e0) ? ei : (e0 - 1);
            int s = colt[ec];
            float4 v = x4[s * 2 + c];
            if (ei < e0) { aT.x += v.x; aT.y += v.y; aT.z += v.z; aT.w += v.w; }
        }

        int b1 = rpi[node], e1 = rpi[node + 1];
        for (int e = b1; e < e1; e += 16) {
            int ei = e + g;
            int ec = (ei < e1) ? ei : (e1 - 1);
            int s = coli[ec];
            float4 v = x4[s * 2 + c];
            if (ei < e1) { aM.x += v.x; aM.y += v.y; aM.z += v.z; aM.w += v.w; }
        }

#pragma unroll
        for (int off = 2; off <= 16; off <<= 1) {
            aT.x += __shfl_xor_sync(0xffffffffu, aT.x, off);
            aT.y += __shfl_xor_sync(0xffffffffu, aT.y, off);
            aT.z += __shfl_xor_sync(0xffffffffu, aT.z, off);
            aT.w += __shfl_xor_sync(0xffffffffu, aT.w, off);
            aM.x += __shfl_xor_sync(0xffffffffu, aM.x, off);
            aM.y += __shfl_xor_sync(0xffffffffu, aM.y, off);
            aM.z += __shfl_xor_sync(0xffffffffu, aM.z, off);
            aM.w += __shfl_xor_sync(0xffffffffu, aM.w, off);
        }
        float invd = 1.0f / fmaxf((float)(e1 - b1), 1.0f);
        aM.x *= invd; aM.y *= invd; aM.z *= invd; aM.w *= invd;

        if (lane < 2) {
            float4 xv = x4[node * 2 + lane];
            vbase[j * 8 + lane * 4 + 0] = make_float4(aT.x, aM.x, xv.x, 0.f);
            vbase[j * 8 + lane * 4 + 1] = make_float4(aT.y, aM.y, xv.y, 0.f);
            vbase[j * 8 + lane * 4 + 2] = make_float4(aT.z, aM.z, xv.z, 0.f);
            vbase[j * 8 + lane * 4 + 3] = make_float4(aT.w, aM.w, xv.w, 0.f);
        }
    }
    __syncwarp();

    float acc0 = sB[lane], acc1 = sB[lane], acc2 = sB[lane], acc3 = sB[lane];
#pragma unroll
    for (int ci = 0; ci < 6; ci++) {
        float4 w = sW4[ci * 32 + lane];
        float4 v0 = vbase[0 * 8 + ci];
        float4 v1 = vbase[1 * 8 + ci];
        float4 v2 = vbase[2 * 8 + ci];
        float4 v3 = vbase[3 * 8 + ci];
        acc0 += v0.x * w.x + v0.y * w.y + v0.z * w.z;
        acc1 += v1.x * w.x + v1.y * w.y + v1.z * w.z;
        acc2 += v2.x * w.x + v2.y * w.y + v2.z * w.z;
        acc3 += v3.x * w.x + v3.y * w.y + v3.z * w.z;
    }
    float accs[4] = {acc0, acc1, acc2, acc3};
#pragma unroll
    for (int j = 0; j < 4; j++) {
        int node = node0 + j;
        if (node < n) hout[node * 32 + lane] = fmaxf(accs[j], 0.f);
    }
}

// ---------------------------------------------------------------------------
// Fused LAST layer (32->64 + projection residual). WPB warps x 4 nodes.
// ---------------------------------------------------------------------------
__global__ void __launch_bounds__(WPB * 32)
fused_last2(const float* __restrict__ h,
            const int* __restrict__ rpt, const int* __restrict__ colt,
            const int* __restrict__ rpi, const int* __restrict__ coli,
            const float* __restrict__ Wt, const float* __restrict__ Wi,
            const float* __restrict__ Wr, const float* __restrict__ b,
            const float* __restrict__ Wp,
            float* __restrict__ out, int n) {
    __shared__ float4 sW4a[32 * 32];         // 16 KB
    __shared__ float4 sW4b[32 * 32];         // 16 KB
    __shared__ float4 sV[WPB * 4 * 32];      // 24 KB

    for (int i = threadIdx.x; i < 32 * 32; i += blockDim.x) {
        int ci = i >> 5, l = i & 31;
        sW4a[i] = make_float4(Wt[ci * 64 + l],      Wi[ci * 64 + l],      Wr[ci * 64 + l],      Wp[ci * 64 + l]);
        sW4b[i] = make_float4(Wt[ci * 64 + l + 32], Wi[ci * 64 + l + 32], Wr[ci * 64 + l + 32], Wp[ci * 64 + l + 32]);
    }
    __syncthreads();

    int warp = threadIdx.x >> 5, lane = threadIdx.x & 31;
    int node0 = (blockIdx.x * WPB + warp) * 4;
    if (node0 >= n) return;
    int g = lane >> 3, c = lane & 7;
    const float4* h4 = (const float4*)h;
    float4* vbase = &sV[warp * 128];

    float bias0 = b[lane], bias1 = b[lane + 32];

#pragma unroll
    for (int j = 0; j < 4; j++) {
        int node = node0 + j;
        if (node >= n) break;

        float4 aT = make_float4(0.f, 0.f, 0.f, 0.f);
        float4 aM = make_float4(0.f, 0.f, 0.f, 0.f);

        int b0 = rpt[node], e0 = rpt[node + 1];
        for (int e = b0; e < e0; e += 4) {
            int ei = e + g;
            int ec = (ei < e0) ? ei : (e0 - 1);
            int s = colt[ec];
            float4 v = h4[s * 8 + c];
            if (ei < e0) { aT.x += v.x; aT.y += v.y; aT.z += v.z; aT.w += v.w; }
        }

        int b1 = rpi[node], e1 = rpi[node + 1];
        for (int e = b1; e < e1; e += 4) {
            int ei = e + g;
            int ec = (ei < e1) ? ei : (e1 - 1);
            int s = coli[ec];
            float4 v = h4[s * 8 + c];
            if (ei < e1) { aM.x += v.x; aM.y += v.y; aM.z += v.z; aM.w += v.w; }
        }

#pragma unroll
        for (int off = 8; off <= 16; off <<= 1) {
            aT.x += __shfl_xor_sync(0xffffffffu, aT.x, off);
            aT.y += __shfl_xor_sync(0xffffffffu, aT.y, off);
            aT.z += __shfl_xor_sync(0xffffffffu, aT.z, off);
            aT.w += __shfl_xor_sync(0xffffffffu, aT.w, off);
            aM.x += __shfl_xor_sync(0xffffffffu, aM.x, off);
            aM.y += __shfl_xor_sync(0xffffffffu, aM.y, off);
            aM.z += __shfl_xor_sync(0xffffffffu, aM.z, off);
            aM.w += __shfl_xor_sync(0xffffffffu, aM.w, off);
        }
        float invd = 1.0f / fmaxf((float)(e1 - b1), 1.0f);
        aM.x *= invd; aM.y *= invd; aM.z *= invd; aM.w *= invd;

        if (lane < 8) {
            float4 hv = h4[node * 8 + lane];
            vbase[j * 32 + lane * 4 + 0] = make_float4(aT.x, aM.x, hv.x, 0.f);
            vbase[j * 32 + lane * 4 + 1] = make_float4(aT.y, aM.y, hv.y, 0.f);
            vbase[j * 32 + lane * 4 + 2] = make_float4(aT.z, aM.z, hv.z, 0.f);
            vbase[j * 32 + lane * 4 + 3] = make_float4(aT.w, aM.w, hv.w, 0.f);
        }
    }
    __syncwarp();

    float a0[4], a1[4], p0[4], p1[4];
#pragma unroll
    for (int j = 0; j < 4; j++) { a0[j] = bias0; a1[j] = bias1; p0[j] = 0.f; p1[j] = 0.f; }

#pragma unroll
    for (int ci = 0; ci < 32; ci++) {
        float4 wa = sW4a[ci * 32 + lane];
        float4 wb = sW4b[ci * 32 + lane];
#pragma unroll
        for (int j = 0; j < 4; j++) {
            float4 v = vbase[j * 32 + ci];
            a0[j] += v.x * wa.x + v.y * wa.y + v.z * wa.z;
            p0[j] += v.z * wa.w;
            a1[j] += v.x * wb.x + v.y * wb.y + v.z * wb.z;
            p1[j] += v.z * wb.w;
        }
    }
#pragma unroll
    for (int j = 0; j < 4; j++) {
        int node = node0 + j;
        if (node < n) {
            out[node * 64 + lane]      = fmaxf(a0[j], 0.f) + p0[j];
            out[node * 64 + lane + 32] = fmaxf(a1[j], 0.f) + p1[j];
        }
    }
}

// ---------------------------------------------------------------------------
// Launch
// ---------------------------------------------------------------------------
extern "C" void kernel_launch(void* const* d_in, const int* in_sizes, int n_in,
                              void* d_out, int out_size) {
    const float* x        = (const float*)d_in[0];
    const int*   ei_t     = (const int*)d_in[1];
    const int*   ei_i     = (const int*)d_in[2];
    const float* head_Wt  = (const float*)d_in[3];
    const float* head_Wi  = (const float*)d_in[4];
    const float* head_Wr  = (const float*)d_in[5];
    const float* head_b   = (const float*)d_in[6];
    const float* blk_Wt   = (const float*)d_in[7];
    const float* blk_Wi   = (const float*)d_in[8];
    const float* blk_Wr   = (const float*)d_in[9];
    const float* blk_b    = (const float*)d_in[10];
    const float* last_Wt  = (const float*)d_in[11];
    const float* last_Wi  = (const float*)d_in[12];
    const float* last_Wr  = (const float*)d_in[13];
    const float* last_b   = (const float*)d_in[14];
    const float* last_proj= (const float*)d_in[15];

    const int n  = in_sizes[0] / 6;      // 100000
    const int Et = in_sizes[1] / 2;      // 100000
    const int Ei = in_sizes[2] / 2;      // 3200000

    float *h, *h2, *x8;
    int *degt, *degi, *rpt, *rpi, *colt, *coli, *bst, *bsi;
    cudaGetSymbolAddress((void**)&h,    g_h);
    cudaGetSymbolAddress((void**)&h2,   g_h2);
    cudaGetSymbolAddress((void**)&x8,   g_x8);
    cudaGetSymbolAddress((void**)&degt, g_deg_t);
    cudaGetSymbolAddress((void**)&degi, g_deg_i);
    cudaGetSymbolAddress((void**)&rpt,  g_rpt);
    cudaGetSymbolAddress((void**)&rpi,  g_rpi);
    cudaGetSymbolAddress((void**)&bst,  g_bsum_t);
    cudaGetSymbolAddress((void**)&bsi,  g_bsum_i);
    cudaGetSymbolAddress((void**)&colt, g_col_t);
    cudaGetSymbolAddress((void**)&coli, g_col_i);

    const int T = 256;
    const int TB = WPB * 32;           // 384
    int nb = (n + 1023) / 1024;
    int nodeBlocks = (n + NPB - 1) / NPB;

    // --- CSR build ---
    zero2_kernel<<<(n + T - 1) / T, T>>>(degt, degi, n);
    count_kernel<<<(Et + T - 1) / T, T>>>(ei_t + Et, Et, degt);
    count_kernel<<<(Ei + T - 1) / T, T>>>(ei_i + Ei, Ei, degi);

    repack_x8<<<(n * 8 + T - 1) / T, T>>>(x, x8, n);

    scan_p1<<<nb, 1024>>>(degt, rpt, bst, n);
    scan_p1<<<nb, 1024>>>(degi, rpi, bsi, n);
    scan_p2<<<1, 1024>>>(bst, nb);
    scan_p2<<<1, 1024>>>(bsi, nb);
    scan_p3<<<(n + T) / T, T>>>(rpt, bst, degt, n, Et);
    scan_p3<<<(n + T) / T, T>>>(rpi, bsi, degi, n, Ei);
    fill_kernel<<<(Et + T - 1) / T, T>>>(ei_t, ei_t + Et, Et, degt, colt);
    fill_kernel<<<(Ei + T - 1) / T, T>>>(ei_i, ei_i + Ei, Ei, degi, coli);

    // --- head: 6 -> 32 ---
    fused_head2<<<nodeBlocks, TB>>>(x8, rpt, colt, rpi, coli,
                                    head_Wt, head_Wi, head_Wr, head_b, h, n);

    // --- 3 residual blocks: 32 -> 32 ---
    for (int i = 0; i < 3; i++) {
        fused_hidden2<<<nodeBlocks, TB>>>(h, rpt, colt, rpi, coli,
                                          blk_Wt + i * 32 * 32, blk_Wi + i * 32 * 32,
                                          blk_Wr + i * 32 * 32, blk_b + i * 32,
                                          h2, n);
        float* tmp = h; h = h2; h2 = tmp;
    }

    // --- last: 32 -> 64 ---
    fused_last2<<<nodeBlocks, TB>>>(h, rpt, colt, rpi, coli,
                                    last_Wt, last_Wi, last_Wr, last_b, last_proj,
                                    (float*)d_out, n);
}